// round 1
// baseline (speedup 1.0000x reference)
#include <cuda_runtime.h>
#include <math.h>

#define D_MODEL 1024
#define NHEAD   16
#define DK      64
#define BATCH   2
#define SEQ     2048
#define MTOT    (BATCH*SEQ)   // 4096

// Scratch (allocation-free: __device__ globals)
__device__ float g_Q[MTOT * D_MODEL];
__device__ float g_K[MTOT * D_MODEL];
__device__ float g_V[MTOT * D_MODEL];
__device__ float g_CTX[MTOT * D_MODEL];

// ---------------------------------------------------------------------------
// C[M][N] = A[M][K] @ W[N][K]^T + bias[N]   (M=4096, N=K=1024)
// 64x64 tile per block, BK=16, 256 threads, 4x4 micro-tile per thread.
// Tiles stored k-major-transposed in smem so the inner loop is 2x LDS.128
// (one broadcast, one conflict-free) per 16 FFMA.
// ---------------------------------------------------------------------------
__global__ void __launch_bounds__(256) gemm_nt_bias(
    const float* __restrict__ A, const float* __restrict__ W,
    const float* __restrict__ bias, float* __restrict__ C)
{
    const int Kdim = D_MODEL, N = D_MODEL;
    __shared__ float As[16][68];   // [k][m]
    __shared__ float Ws[16][68];   // [k][n]
    int tid = threadIdx.x;
    int tx = tid & 15, ty = tid >> 4;
    int m0 = blockIdx.y * 64, n0 = blockIdx.x * 64;
    int lr = tid >> 2;             // 0..63 (tile row)
    int lc = (tid & 3) << 2;       // 0,4,8,12 (k within tile)
    float acc[4][4] = {};

    for (int k0 = 0; k0 < Kdim; k0 += 16) {
        float4 a = *(const float4*)&A[(size_t)(m0 + lr) * Kdim + k0 + lc];
        float4 w = *(const float4*)&W[(size_t)(n0 + lr) * Kdim + k0 + lc];
        As[lc+0][lr] = a.x; As[lc+1][lr] = a.y; As[lc+2][lr] = a.z; As[lc+3][lr] = a.w;
        Ws[lc+0][lr] = w.x; Ws[lc+1][lr] = w.y; Ws[lc+2][lr] = w.z; Ws[lc+3][lr] = w.w;
        __syncthreads();
        #pragma unroll
        for (int k = 0; k < 16; k++) {
            float4 av = *(const float4*)&As[k][ty * 4];
            float4 wv = *(const float4*)&Ws[k][tx * 4];
            float am[4] = {av.x, av.y, av.z, av.w};
            float wn[4] = {wv.x, wv.y, wv.z, wv.w};
            #pragma unroll
            for (int i = 0; i < 4; i++)
                #pragma unroll
                for (int j = 0; j < 4; j++)
                    acc[i][j] = fmaf(am[i], wn[j], acc[i][j]);
        }
        __syncthreads();
    }

    float4 bv = *(const float4*)&bias[n0 + tx * 4];
    float bb[4] = {bv.x, bv.y, bv.z, bv.w};
    #pragma unroll
    for (int i = 0; i < 4; i++) {
        float4 r;
        r.x = acc[i][0] + bb[0];
        r.y = acc[i][1] + bb[1];
        r.z = acc[i][2] + bb[2];
        r.w = acc[i][3] + bb[3];
        *(float4*)&C[(size_t)(m0 + ty * 4 + i) * N + n0 + tx * 4] = r;
    }
}

// ---------------------------------------------------------------------------
// Flash attention, fp32. One block = 64 queries of one (b,h).
// KV tiles of 32. Online softmax. 256 threads:
//   S phase:  thread (tx,ty) owns s[4 q][2 k]   (q0=ty*4, k0=tx*2)
//   PV phase: thread (tx,ty) owns o[4 q][4 d]   (q0=ty*4, d0=tx*4)
// Row stats reduced across the 16 tx-lanes via shfl_xor (same ty = same
// contiguous 16-lane group within a warp).
// ---------------------------------------------------------------------------
__global__ void __launch_bounds__(256) attn_kernel(
    const float* __restrict__ Q, const float* __restrict__ K,
    const float* __restrict__ V, float* __restrict__ O)
{
    __shared__ float Qs[64][68];   // [d][q]
    __shared__ float Ks[64][36];   // [d][j]
    __shared__ float Vs[32][68];   // [j][d]
    __shared__ float Ps[32][68];   // [j][i]

    int tid = threadIdx.x;
    int tx = tid & 15, ty = tid >> 4;
    int q0 = blockIdx.x * 64;
    int bh = blockIdx.y;
    int b = bh >> 4, h = bh & 15;
    const size_t base = (size_t)b * SEQ * D_MODEL + (size_t)h * DK;
    const float* qb = Q + base;
    const float* kb = K + base;
    const float* vb = V + base;

    // Load Q tile (64q x 64d) transposed into Qs[d][q]
    {
        int qr = tid >> 4;
        int d0 = (tid & 15) << 2;
        #pragma unroll
        for (int qq = 0; qq < 64; qq += 16) {
            float4 v4 = *(const float4*)&qb[(size_t)(q0 + qq + qr) * D_MODEL + d0];
            Qs[d0+0][qq+qr] = v4.x; Qs[d0+1][qq+qr] = v4.y;
            Qs[d0+2][qq+qr] = v4.z; Qs[d0+3][qq+qr] = v4.w;
        }
    }

    const float NEG_INF = __int_as_float(0xff800000);
    float m_i[4], l_i[4], o[4][4];
    #pragma unroll
    for (int i = 0; i < 4; i++) {
        m_i[i] = NEG_INF; l_i[i] = 0.f;
        #pragma unroll
        for (int j = 0; j < 4; j++) o[i][j] = 0.f;
    }

    for (int kt = 0; kt < SEQ; kt += 32) {
        __syncthreads();   // protect Ks/Vs/Ps from previous iteration's readers
        // Load K tile (32j x 64d) transposed to Ks[d][j]; V natural to Vs[j][d]
        {
            int jr = tid >> 4;
            int d0 = (tid & 15) << 2;
            #pragma unroll
            for (int jj = 0; jj < 32; jj += 16) {
                float4 kk = *(const float4*)&kb[(size_t)(kt + jj + jr) * D_MODEL + d0];
                Ks[d0+0][jj+jr] = kk.x; Ks[d0+1][jj+jr] = kk.y;
                Ks[d0+2][jj+jr] = kk.z; Ks[d0+3][jj+jr] = kk.w;
                *(float4*)&Vs[jj+jr][d0] =
                    *(const float4*)&vb[(size_t)(kt + jj + jr) * D_MODEL + d0];
            }
        }
        __syncthreads();

        // S = (Q k-tile) : s[4][2]
        float s[4][2] = {};
        #pragma unroll 8
        for (int d = 0; d < 64; d++) {
            float4 qv = *(const float4*)&Qs[d][ty * 4];
            float2 kv = *(const float2*)&Ks[d][tx * 2];
            s[0][0] = fmaf(qv.x, kv.x, s[0][0]);
            s[1][0] = fmaf(qv.y, kv.x, s[1][0]);
            s[2][0] = fmaf(qv.z, kv.x, s[2][0]);
            s[3][0] = fmaf(qv.w, kv.x, s[3][0]);
            s[0][1] = fmaf(qv.x, kv.y, s[0][1]);
            s[1][1] = fmaf(qv.y, kv.y, s[1][1]);
            s[2][1] = fmaf(qv.z, kv.y, s[2][1]);
            s[3][1] = fmaf(qv.w, kv.y, s[3][1]);
        }

        // Online softmax update
        float p[4][2];
        #pragma unroll
        for (int i = 0; i < 4; i++) {
            s[i][0] *= 0.125f;  // 1/sqrt(64)
            s[i][1] *= 0.125f;
            float t = fmaxf(s[i][0], s[i][1]);
            #pragma unroll
            for (int off = 1; off < 16; off <<= 1)
                t = fmaxf(t, __shfl_xor_sync(0xffffffffu, t, off));
            float m_new = fmaxf(m_i[i], t);
            float sc = __expf(m_i[i] - m_new);
            p[i][0] = __expf(s[i][0] - m_new);
            p[i][1] = __expf(s[i][1] - m_new);
            float rs = p[i][0] + p[i][1];
            #pragma unroll
            for (int off = 1; off < 16; off <<= 1)
                rs += __shfl_xor_sync(0xffffffffu, rs, off);
            l_i[i] = l_i[i] * sc + rs;
            m_i[i] = m_new;
            #pragma unroll
            for (int j = 0; j < 4; j++) o[i][j] *= sc;
        }

        // Write P transposed: Ps[j][i], vectorized over i
        #pragma unroll
        for (int jj = 0; jj < 2; jj++) {
            float4 pv;
            pv.x = p[0][jj]; pv.y = p[1][jj]; pv.z = p[2][jj]; pv.w = p[3][jj];
            *(float4*)&Ps[tx * 2 + jj][ty * 4] = pv;
        }
        __syncthreads();

        // O += P @ V
        #pragma unroll 8
        for (int j = 0; j < 32; j++) {
            float4 pv = *(const float4*)&Ps[j][ty * 4];
            float4 vv = *(const float4*)&Vs[j][tx * 4];
            float pa[4] = {pv.x, pv.y, pv.z, pv.w};
            float va[4] = {vv.x, vv.y, vv.z, vv.w};
            #pragma unroll
            for (int i = 0; i < 4; i++)
                #pragma unroll
                for (int dd = 0; dd < 4; dd++)
                    o[i][dd] = fmaf(pa[i], va[dd], o[i][dd]);
        }
    }

    // Epilogue: normalize and store context (same [m][h*64+d] layout)
    float* ob = O + base;
    #pragma unroll
    for (int i = 0; i < 4; i++) {
        float inv = 1.f / l_i[i];
        float4 r;
        r.x = o[i][0] * inv; r.y = o[i][1] * inv;
        r.z = o[i][2] * inv; r.w = o[i][3] * inv;
        *(float4*)&ob[(size_t)(q0 + ty * 4 + i) * D_MODEL + tx * 4] = r;
    }
}

// ---------------------------------------------------------------------------
extern "C" void kernel_launch(void* const* d_in, const int* in_sizes, int n_in,
                              void* d_out, int out_size)
{
    const float* x  = (const float*)d_in[0];
    const float* Wq = (const float*)d_in[1];
    const float* bq = (const float*)d_in[2];
    const float* Wk = (const float*)d_in[3];
    const float* bk = (const float*)d_in[4];
    const float* Wv = (const float*)d_in[5];
    const float* bv = (const float*)d_in[6];
    const float* Wo = (const float*)d_in[7];
    const float* bo = (const float*)d_in[8];
    float* out = (float*)d_out;

    float *gq, *gk, *gv, *gctx;
    cudaGetSymbolAddress((void**)&gq,   g_Q);
    cudaGetSymbolAddress((void**)&gk,   g_K);
    cudaGetSymbolAddress((void**)&gv,   g_V);
    cudaGetSymbolAddress((void**)&gctx, g_CTX);

    dim3 gg(D_MODEL / 64, MTOT / 64);           // (16, 64)
    gemm_nt_bias<<<gg, 256>>>(x, Wq, bq, gq);
    gemm_nt_bias<<<gg, 256>>>(x, Wk, bk, gk);
    gemm_nt_bias<<<gg, 256>>>(x, Wv, bv, gv);
    attn_kernel<<<dim3(SEQ / 64, BATCH * NHEAD), 256>>>(gq, gk, gv, gctx);
    gemm_nt_bias<<<gg, 256>>>(gctx, Wo, bo, out);
}

// round 3
// speedup vs baseline: 1.3683x; 1.3683x over previous
#include <cuda_runtime.h>
#include <cuda_bf16.h>
#include <math.h>
#include <stdint.h>

#define D_MODEL 1024
#define NHEAD   16
#define DK      64
#define BATCH   2
#define SEQ     2048
#define MTOT    (BATCH*SEQ)   // 4096

// Scratch (allocation-free: __device__ globals)
__device__ float g_Q[MTOT * D_MODEL];
__device__ float g_K[MTOT * D_MODEL];
__device__ float g_V[MTOT * D_MODEL];
__device__ float g_CTX[MTOT * D_MODEL];

// ============================================================================
// helpers
// ============================================================================
__device__ __forceinline__ uint32_t s2u(const void* p) {
    uint32_t a;
    asm("{ .reg .u64 t; cvta.to.shared.u64 t, %1; cvt.u32.u64 %0, t; }"
        : "=r"(a) : "l"(p));
    return a;
}

#define LDSM_X4(R, addr)                                                    \
    asm volatile("ldmatrix.sync.aligned.m8n8.x4.shared.b16 "                \
                 "{%0,%1,%2,%3}, [%4];"                                     \
                 : "=r"((R)[0]), "=r"((R)[1]), "=r"((R)[2]), "=r"((R)[3])   \
                 : "r"(addr))

#define MMA16816(C, A, B0, B1)                                              \
    asm volatile("mma.sync.aligned.m16n8k16.row.col.f32.bf16.bf16.f32 "     \
                 "{%0,%1,%2,%3}, {%4,%5,%6,%7}, {%8,%9}, {%0,%1,%2,%3};"    \
                 : "+f"((C)[0]), "+f"((C)[1]), "+f"((C)[2]), "+f"((C)[3])   \
                 : "r"((A)[0]), "r"((A)[1]), "r"((A)[2]), "r"((A)[3]),      \
                   "r"(B0), "r"(B1))

__device__ __forceinline__ void pack_hilo(float a, float b,
                                          uint32_t& h, uint32_t& l) {
    __nv_bfloat162 hv;
    hv.x = __float2bfloat16(a);
    hv.y = __float2bfloat16(b);
    float ra = a - __bfloat162float(hv.x);
    float rb = b - __bfloat162float(hv.y);
    __nv_bfloat162 lv;
    lv.x = __float2bfloat16(ra);
    lv.y = __float2bfloat16(rb);
    h = *(uint32_t*)&hv;
    l = *(uint32_t*)&lv;
}

// ============================================================================
// HMMA GEMM with bf16 hi/lo split:
//   C[M][N] = A[M][K] @ W[N][K]^T + bias[N]     (M=4096, N=K=1024)
// CTA tile 128x128, K-stage 32, 256 threads = 8 warps (4 m x 2 n),
// warp tile 32x64. Fragments via ldmatrix from smem (row stride 40 bf16 =
// 80 B -> conflict-free LDSM phases).
// ============================================================================
#define RS 40                      // bf16 elements per smem row (80 B)

__global__ void __launch_bounds__(256) gemm_mma(
    const float* __restrict__ A, const float* __restrict__ W,
    const float* __restrict__ bias, float* __restrict__ C)
{
    __shared__ __align__(16) __nv_bfloat16 sAh[128 * RS];
    __shared__ __align__(16) __nv_bfloat16 sAl[128 * RS];
    __shared__ __align__(16) __nv_bfloat16 sWh[128 * RS];
    __shared__ __align__(16) __nv_bfloat16 sWl[128 * RS];

    const int tid  = threadIdx.x;
    const int lane = tid & 31;
    const int wid  = tid >> 5;
    const int wm   = wid & 3;          // m-warp: rows wm*32
    const int wn   = wid >> 2;         // n-warp: cols wn*64
    const int m0   = blockIdx.y * 128;
    const int n0   = blockIdx.x * 128;

    float acc[2][8][4] = {};

    // ldmatrix lane addressing: group g supplies rows of the four 8x8 tiles
    const int g    = lane >> 3;
    const int rofs = ((g & 1) << 3) + (lane & 7);   // row within 16
    const int kofs = (g >> 1) << 3;                 // k col: 0 or 8

    const uint32_t aH = s2u(sAh) + (((wm * 32 + rofs) * RS + kofs) << 1);
    const uint32_t aL = s2u(sAl) + (((wm * 32 + rofs) * RS + kofs) << 1);
    const uint32_t bH = s2u(sWh) + (((wn * 64 + rofs) * RS + kofs) << 1);
    const uint32_t bL = s2u(sWl) + (((wn * 64 + rofs) * RS + kofs) << 1);

    // staging: thread -> (row, k-half)
    const int srow = tid >> 1;
    const int skh  = (tid & 1) << 4;
    const float* Aptr = A + (size_t)(m0 + srow) * D_MODEL + skh;
    const float* Wptr = W + (size_t)(n0 + srow) * D_MODEL + skh;

    float4 ra[4], rw[4];
    #pragma unroll
    for (int j = 0; j < 4; ++j) {
        ra[j] = *(const float4*)(Aptr + j * 4);
        rw[j] = *(const float4*)(Wptr + j * 4);
    }

    #pragma unroll 1
    for (int s = 0; s < 32; ++s) {
        if (s) __syncthreads();     // previous stage's readers done

        // convert + store current stage
        {
            float fa[16] = {ra[0].x, ra[0].y, ra[0].z, ra[0].w,
                            ra[1].x, ra[1].y, ra[1].z, ra[1].w,
                            ra[2].x, ra[2].y, ra[2].z, ra[2].w,
                            ra[3].x, ra[3].y, ra[3].z, ra[3].w};
            float fw[16] = {rw[0].x, rw[0].y, rw[0].z, rw[0].w,
                            rw[1].x, rw[1].y, rw[1].z, rw[1].w,
                            rw[2].x, rw[2].y, rw[2].z, rw[2].w,
                            rw[3].x, rw[3].y, rw[3].z, rw[3].w};
            uint32_t h[8], l[8];
            #pragma unroll
            for (int j = 0; j < 8; ++j) pack_hilo(fa[2*j], fa[2*j+1], h[j], l[j]);
            *(uint4*)&sAh[srow * RS + skh]     = make_uint4(h[0], h[1], h[2], h[3]);
            *(uint4*)&sAh[srow * RS + skh + 8] = make_uint4(h[4], h[5], h[6], h[7]);
            *(uint4*)&sAl[srow * RS + skh]     = make_uint4(l[0], l[1], l[2], l[3]);
            *(uint4*)&sAl[srow * RS + skh + 8] = make_uint4(l[4], l[5], l[6], l[7]);
            #pragma unroll
            for (int j = 0; j < 8; ++j) pack_hilo(fw[2*j], fw[2*j+1], h[j], l[j]);
            *(uint4*)&sWh[srow * RS + skh]     = make_uint4(h[0], h[1], h[2], h[3]);
            *(uint4*)&sWh[srow * RS + skh + 8] = make_uint4(h[4], h[5], h[6], h[7]);
            *(uint4*)&sWl[srow * RS + skh]     = make_uint4(l[0], l[1], l[2], l[3]);
            *(uint4*)&sWl[srow * RS + skh + 8] = make_uint4(l[4], l[5], l[6], l[7]);
        }

        // prefetch next stage while this one computes
        if (s + 1 < 32) {
            const float* An = Aptr + (s + 1) * 32;
            const float* Wn = Wptr + (s + 1) * 32;
            #pragma unroll
            for (int j = 0; j < 4; ++j) {
                ra[j] = *(const float4*)(An + j * 4);
                rw[j] = *(const float4*)(Wn + j * 4);
            }
        }
        __syncthreads();            // stores visible

        #pragma unroll
        for (int kk = 0; kk < 2; ++kk) {
            const uint32_t ko = kk << 5;   // k16 * 2 bytes
            uint32_t ah[2][4], al[2][4];
            LDSM_X4(ah[0], aH + ko);
            LDSM_X4(ah[1], aH + 16 * RS * 2 + ko);
            LDSM_X4(al[0], aL + ko);
            LDSM_X4(al[1], aL + 16 * RS * 2 + ko);
            #pragma unroll
            for (int ng = 0; ng < 4; ++ng) {
                uint32_t bh[4], bl[4];
                LDSM_X4(bh, bH + ng * 16 * RS * 2 + ko);
                LDSM_X4(bl, bL + ng * 16 * RS * 2 + ko);
                #pragma unroll
                for (int mt = 0; mt < 2; ++mt) {
                    MMA16816(acc[mt][2*ng],   ah[mt], bh[0], bh[2]);
                    MMA16816(acc[mt][2*ng],   ah[mt], bl[0], bl[2]);
                    MMA16816(acc[mt][2*ng],   al[mt], bh[0], bh[2]);
                    MMA16816(acc[mt][2*ng+1], ah[mt], bh[1], bh[3]);
                    MMA16816(acc[mt][2*ng+1], ah[mt], bl[1], bl[3]);
                    MMA16816(acc[mt][2*ng+1], al[mt], bh[1], bh[3]);
                }
            }
        }
    }

    // epilogue
    const int lr = lane >> 2;
    const int lc = (lane & 3) << 1;
    #pragma unroll
    for (int mt = 0; mt < 2; ++mt) {
        const int row = m0 + wm * 32 + mt * 16 + lr;
        #pragma unroll
        for (int nt = 0; nt < 8; ++nt) {
            const int col = n0 + wn * 64 + nt * 8 + lc;
            float2 bb = *(const float2*)&bias[col];
            float2 r0, r1;
            r0.x = acc[mt][nt][0] + bb.x;
            r0.y = acc[mt][nt][1] + bb.y;
            r1.x = acc[mt][nt][2] + bb.x;
            r1.y = acc[mt][nt][3] + bb.y;
            *(float2*)&C[(size_t)row * D_MODEL + col]       = r0;
            *(float2*)&C[(size_t)(row + 8) * D_MODEL + col] = r1;
        }
    }
}

// ---------------------------------------------------------------------------
// Flash attention, fp32 (unchanged — known correct).
// ---------------------------------------------------------------------------
__global__ void __launch_bounds__(256) attn_kernel(
    const float* __restrict__ Q, const float* __restrict__ K,
    const float* __restrict__ V, float* __restrict__ O)
{
    __shared__ float Qs[64][68];   // [d][q]
    __shared__ float Ks[64][36];   // [d][j]
    __shared__ float Vs[32][68];   // [j][d]
    __shared__ float Ps[32][68];   // [j][i]

    int tid = threadIdx.x;
    int tx = tid & 15, ty = tid >> 4;
    int q0 = blockIdx.x * 64;
    int bh = blockIdx.y;
    int b = bh >> 4, h = bh & 15;
    const size_t base = (size_t)b * SEQ * D_MODEL + (size_t)h * DK;
    const float* qb = Q + base;
    const float* kb = K + base;
    const float* vb = V + base;

    {
        int qr = tid >> 4;
        int d0 = (tid & 15) << 2;
        #pragma unroll
        for (int qq = 0; qq < 64; qq += 16) {
            float4 v4 = *(const float4*)&qb[(size_t)(q0 + qq + qr) * D_MODEL + d0];
            Qs[d0+0][qq+qr] = v4.x; Qs[d0+1][qq+qr] = v4.y;
            Qs[d0+2][qq+qr] = v4.z; Qs[d0+3][qq+qr] = v4.w;
        }
    }

    const float NEG_INF = __int_as_float(0xff800000);
    float m_i[4], l_i[4], o[4][4];
    #pragma unroll
    for (int i = 0; i < 4; i++) {
        m_i[i] = NEG_INF; l_i[i] = 0.f;
        #pragma unroll
        for (int j = 0; j < 4; j++) o[i][j] = 0.f;
    }

    for (int kt = 0; kt < SEQ; kt += 32) {
        __syncthreads();
        {
            int jr = tid >> 4;
            int d0 = (tid & 15) << 2;
            #pragma unroll
            for (int jj = 0; jj < 32; jj += 16) {
                float4 kk = *(const float4*)&kb[(size_t)(kt + jj + jr) * D_MODEL + d0];
                Ks[d0+0][jj+jr] = kk.x; Ks[d0+1][jj+jr] = kk.y;
                Ks[d0+2][jj+jr] = kk.z; Ks[d0+3][jj+jr] = kk.w;
                *(float4*)&Vs[jj+jr][d0] =
                    *(const float4*)&vb[(size_t)(kt + jj + jr) * D_MODEL + d0];
            }
        }
        __syncthreads();

        float s[4][2] = {};
        #pragma unroll 8
        for (int d = 0; d < 64; d++) {
            float4 qv = *(const float4*)&Qs[d][ty * 4];
            float2 kv = *(const float2*)&Ks[d][tx * 2];
            s[0][0] = fmaf(qv.x, kv.x, s[0][0]);
            s[1][0] = fmaf(qv.y, kv.x, s[1][0]);
            s[2][0] = fmaf(qv.z, kv.x, s[2][0]);
            s[3][0] = fmaf(qv.w, kv.x, s[3][0]);
            s[0][1] = fmaf(qv.x, kv.y, s[0][1]);
            s[1][1] = fmaf(qv.y, kv.y, s[1][1]);
            s[2][1] = fmaf(qv.z, kv.y, s[2][1]);
            s[3][1] = fmaf(qv.w, kv.y, s[3][1]);
        }

        float p[4][2];
        #pragma unroll
        for (int i = 0; i < 4; i++) {
            s[i][0] *= 0.125f;
            s[i][1] *= 0.125f;
            float t = fmaxf(s[i][0], s[i][1]);
            #pragma unroll
            for (int off = 1; off < 16; off <<= 1)
                t = fmaxf(t, __shfl_xor_sync(0xffffffffu, t, off));
            float m_new = fmaxf(m_i[i], t);
            float sc = __expf(m_i[i] - m_new);
            p[i][0] = __expf(s[i][0] - m_new);
            p[i][1] = __expf(s[i][1] - m_new);
            float rs = p[i][0] + p[i][1];
            #pragma unroll
            for (int off = 1; off < 16; off <<= 1)
                rs += __shfl_xor_sync(0xffffffffu, rs, off);
            l_i[i] = l_i[i] * sc + rs;
            m_i[i] = m_new;
            #pragma unroll
            for (int j = 0; j < 4; j++) o[i][j] *= sc;
        }

        #pragma unroll
        for (int jj = 0; jj < 2; jj++) {
            float4 pv;
            pv.x = p[0][jj]; pv.y = p[1][jj]; pv.z = p[2][jj]; pv.w = p[3][jj];
            *(float4*)&Ps[tx * 2 + jj][ty * 4] = pv;
        }
        __syncthreads();

        #pragma unroll 8
        for (int j = 0; j < 32; j++) {
            float4 pv = *(const float4*)&Ps[j][ty * 4];
            float4 vv = *(const float4*)&Vs[j][tx * 4];
            float pa[4] = {pv.x, pv.y, pv.z, pv.w};
            float va[4] = {vv.x, vv.y, vv.z, vv.w};
            #pragma unroll
            for (int i = 0; i < 4; i++)
                #pragma unroll
                for (int dd = 0; dd < 4; dd++)
                    o[i][dd] = fmaf(pa[i], va[dd], o[i][dd]);
        }
    }

    float* ob = O + base;
    #pragma unroll
    for (int i = 0; i < 4; i++) {
        float inv = 1.f / l_i[i];
        float4 r;
        r.x = o[i][0] * inv; r.y = o[i][1] * inv;
        r.z = o[i][2] * inv; r.w = o[i][3] * inv;
        *(float4*)&ob[(size_t)(q0 + ty * 4 + i) * D_MODEL + tx * 4] = r;
    }
}

// ---------------------------------------------------------------------------
extern "C" void kernel_launch(void* const* d_in, const int* in_sizes, int n_in,
                              void* d_out, int out_size)
{
    const float* x  = (const float*)d_in[0];
    const float* Wq = (const float*)d_in[1];
    const float* bq = (const float*)d_in[2];
    const float* Wk = (const float*)d_in[3];
    const float* bk = (const float*)d_in[4];
    const float* Wv = (const float*)d_in[5];
    const float* bv = (const float*)d_in[6];
    const float* Wo = (const float*)d_in[7];
    const float* bo = (const float*)d_in[8];
    float* out = (float*)d_out;

    float *gq, *gk, *gv, *gctx;
    cudaGetSymbolAddress((void**)&gq,   g_Q);
    cudaGetSymbolAddress((void**)&gk,   g_K);
    cudaGetSymbolAddress((void**)&gv,   g_V);
    cudaGetSymbolAddress((void**)&gctx, g_CTX);

    dim3 gg(D_MODEL / 128, MTOT / 128);   // (8, 32)
    gemm_mma<<<gg, 256>>>(x, Wq, bq, gq);
    gemm_mma<<<gg, 256>>>(x, Wk, bk, gk);
    gemm_mma<<<gg, 256>>>(x, Wv, bv, gv);
    attn_kernel<<<dim3(SEQ / 64, BATCH * NHEAD), 256>>>(gq, gk, gv, gctx);
    gemm_mma<<<gg, 256>>>(gctx, Wo, bo, out);
}

// round 4
// speedup vs baseline: 2.3980x; 1.7525x over previous
#include <cuda_runtime.h>
#include <cuda_bf16.h>
#include <math.h>
#include <stdint.h>

#define D_MODEL 1024
#define NHEAD   16
#define DK      64
#define BATCH   2
#define SEQ     2048
#define MTOT    (BATCH*SEQ)   // 4096

// Scratch (allocation-free: __device__ globals)
__device__ float g_Q[MTOT * D_MODEL];
__device__ float g_K[MTOT * D_MODEL];
__device__ float g_V[MTOT * D_MODEL];
__device__ float g_CTX[MTOT * D_MODEL];

// ============================================================================
// helpers
// ============================================================================
__device__ __forceinline__ uint32_t s2u(const void* p) {
    uint32_t a;
    asm("{ .reg .u64 t; cvta.to.shared.u64 t, %1; cvt.u32.u64 %0, t; }"
        : "=r"(a) : "l"(p));
    return a;
}

#define LDSM_X4(R, addr)                                                    \
    asm volatile("ldmatrix.sync.aligned.m8n8.x4.shared.b16 "                \
                 "{%0,%1,%2,%3}, [%4];"                                     \
                 : "=r"((R)[0]), "=r"((R)[1]), "=r"((R)[2]), "=r"((R)[3])   \
                 : "r"(addr))

#define LDSM_X4_T(R, addr)                                                  \
    asm volatile("ldmatrix.sync.aligned.m8n8.x4.trans.shared.b16 "          \
                 "{%0,%1,%2,%3}, [%4];"                                     \
                 : "=r"((R)[0]), "=r"((R)[1]), "=r"((R)[2]), "=r"((R)[3])   \
                 : "r"(addr))

#define MMA16816(C, A, B0, B1)                                              \
    asm volatile("mma.sync.aligned.m16n8k16.row.col.f32.bf16.bf16.f32 "     \
                 "{%0,%1,%2,%3}, {%4,%5,%6,%7}, {%8,%9}, {%0,%1,%2,%3};"    \
                 : "+f"((C)[0]), "+f"((C)[1]), "+f"((C)[2]), "+f"((C)[3])   \
                 : "r"((A)[0]), "r"((A)[1]), "r"((A)[2]), "r"((A)[3]),      \
                   "r"(B0), "r"(B1))

__device__ __forceinline__ void pack_hilo(float a, float b,
                                          uint32_t& h, uint32_t& l) {
    __nv_bfloat162 hv;
    hv.x = __float2bfloat16(a);
    hv.y = __float2bfloat16(b);
    float ra = a - __bfloat162float(hv.x);
    float rb = b - __bfloat162float(hv.y);
    __nv_bfloat162 lv;
    lv.x = __float2bfloat16(ra);
    lv.y = __float2bfloat16(rb);
    h = *(uint32_t*)&hv;
    l = *(uint32_t*)&lv;
}

// ============================================================================
// HMMA GEMM with bf16 hi/lo split (unchanged from Round 3 — working):
//   C[M][N] = A[M][K] @ W[N][K]^T + bias[N]     (M=4096, N=K=1024)
// ============================================================================
#define RS 40                      // bf16 elements per smem row (80 B)

__global__ void __launch_bounds__(256) gemm_mma(
    const float* __restrict__ A, const float* __restrict__ W,
    const float* __restrict__ bias, float* __restrict__ C)
{
    __shared__ __align__(16) __nv_bfloat16 sAh[128 * RS];
    __shared__ __align__(16) __nv_bfloat16 sAl[128 * RS];
    __shared__ __align__(16) __nv_bfloat16 sWh[128 * RS];
    __shared__ __align__(16) __nv_bfloat16 sWl[128 * RS];

    const int tid  = threadIdx.x;
    const int lane = tid & 31;
    const int wid  = tid >> 5;
    const int wm   = wid & 3;
    const int wn   = wid >> 2;
    const int m0   = blockIdx.y * 128;
    const int n0   = blockIdx.x * 128;

    float acc[2][8][4] = {};

    const int g    = lane >> 3;
    const int rofs = ((g & 1) << 3) + (lane & 7);
    const int kofs = (g >> 1) << 3;

    const uint32_t aH = s2u(sAh) + (((wm * 32 + rofs) * RS + kofs) << 1);
    const uint32_t aL = s2u(sAl) + (((wm * 32 + rofs) * RS + kofs) << 1);
    const uint32_t bH = s2u(sWh) + (((wn * 64 + rofs) * RS + kofs) << 1);
    const uint32_t bL = s2u(sWl) + (((wn * 64 + rofs) * RS + kofs) << 1);

    const int srow = tid >> 1;
    const int skh  = (tid & 1) << 4;
    const float* Aptr = A + (size_t)(m0 + srow) * D_MODEL + skh;
    const float* Wptr = W + (size_t)(n0 + srow) * D_MODEL + skh;

    float4 ra[4], rw[4];
    #pragma unroll
    for (int j = 0; j < 4; ++j) {
        ra[j] = *(const float4*)(Aptr + j * 4);
        rw[j] = *(const float4*)(Wptr + j * 4);
    }

    #pragma unroll 1
    for (int s = 0; s < 32; ++s) {
        if (s) __syncthreads();

        {
            float fa[16] = {ra[0].x, ra[0].y, ra[0].z, ra[0].w,
                            ra[1].x, ra[1].y, ra[1].z, ra[1].w,
                            ra[2].x, ra[2].y, ra[2].z, ra[2].w,
                            ra[3].x, ra[3].y, ra[3].z, ra[3].w};
            float fw[16] = {rw[0].x, rw[0].y, rw[0].z, rw[0].w,
                            rw[1].x, rw[1].y, rw[1].z, rw[1].w,
                            rw[2].x, rw[2].y, rw[2].z, rw[2].w,
                            rw[3].x, rw[3].y, rw[3].z, rw[3].w};
            uint32_t h[8], l[8];
            #pragma unroll
            for (int j = 0; j < 8; ++j) pack_hilo(fa[2*j], fa[2*j+1], h[j], l[j]);
            *(uint4*)&sAh[srow * RS + skh]     = make_uint4(h[0], h[1], h[2], h[3]);
            *(uint4*)&sAh[srow * RS + skh + 8] = make_uint4(h[4], h[5], h[6], h[7]);
            *(uint4*)&sAl[srow * RS + skh]     = make_uint4(l[0], l[1], l[2], l[3]);
            *(uint4*)&sAl[srow * RS + skh + 8] = make_uint4(l[4], l[5], l[6], l[7]);
            #pragma unroll
            for (int j = 0; j < 8; ++j) pack_hilo(fw[2*j], fw[2*j+1], h[j], l[j]);
            *(uint4*)&sWh[srow * RS + skh]     = make_uint4(h[0], h[1], h[2], h[3]);
            *(uint4*)&sWh[srow * RS + skh + 8] = make_uint4(h[4], h[5], h[6], h[7]);
            *(uint4*)&sWl[srow * RS + skh]     = make_uint4(l[0], l[1], l[2], l[3]);
            *(uint4*)&sWl[srow * RS + skh + 8] = make_uint4(l[4], l[5], l[6], l[7]);
        }

        if (s + 1 < 32) {
            const float* An = Aptr + (s + 1) * 32;
            const float* Wn = Wptr + (s + 1) * 32;
            #pragma unroll
            for (int j = 0; j < 4; ++j) {
                ra[j] = *(const float4*)(An + j * 4);
                rw[j] = *(const float4*)(Wn + j * 4);
            }
        }
        __syncthreads();

        #pragma unroll
        for (int kk = 0; kk < 2; ++kk) {
            const uint32_t ko = kk << 5;
            uint32_t ah[2][4], al[2][4];
            LDSM_X4(ah[0], aH + ko);
            LDSM_X4(ah[1], aH + 16 * RS * 2 + ko);
            LDSM_X4(al[0], aL + ko);
            LDSM_X4(al[1], aL + 16 * RS * 2 + ko);
            #pragma unroll
            for (int ng = 0; ng < 4; ++ng) {
                uint32_t bh[4], bl[4];
                LDSM_X4(bh, bH + ng * 16 * RS * 2 + ko);
                LDSM_X4(bl, bL + ng * 16 * RS * 2 + ko);
                #pragma unroll
                for (int mt = 0; mt < 2; ++mt) {
                    MMA16816(acc[mt][2*ng],   ah[mt], bh[0], bh[2]);
                    MMA16816(acc[mt][2*ng],   ah[mt], bl[0], bl[2]);
                    MMA16816(acc[mt][2*ng],   al[mt], bh[0], bh[2]);
                    MMA16816(acc[mt][2*ng+1], ah[mt], bh[1], bh[3]);
                    MMA16816(acc[mt][2*ng+1], ah[mt], bl[1], bl[3]);
                    MMA16816(acc[mt][2*ng+1], al[mt], bh[1], bh[3]);
                }
            }
        }
    }

    const int lr = lane >> 2;
    const int lc = (lane & 3) << 1;
    #pragma unroll
    for (int mt = 0; mt < 2; ++mt) {
        const int row = m0 + wm * 32 + mt * 16 + lr;
        #pragma unroll
        for (int nt = 0; nt < 8; ++nt) {
            const int col = n0 + wn * 64 + nt * 8 + lc;
            float2 bb = *(const float2*)&bias[col];
            float2 r0, r1;
            r0.x = acc[mt][nt][0] + bb.x;
            r0.y = acc[mt][nt][1] + bb.y;
            r1.x = acc[mt][nt][2] + bb.x;
            r1.y = acc[mt][nt][3] + bb.y;
            *(float2*)&C[(size_t)row * D_MODEL + col]       = r0;
            *(float2*)&C[(size_t)(row + 8) * D_MODEL + col] = r1;
        }
    }
}

// ============================================================================
// HMMA flash attention, hi/lo split everywhere.
// CTA: 128 q rows x one (b,h). 8 warps, warp = 16 q rows. KV tile = 64.
// S = Q@K^T via mma (Q, K hi/lo, 3 passes); softmax in registers;
// P fed straight from C-fragments as A-fragments (hi/lo); O += P@V via mma
// (V hi/lo loaded with ldmatrix.trans).
// Q smem (prologue) is reused as K/V smem (mainloop). 36 KB static.
// ============================================================================
#define AS 72    // smem row stride in bf16 (144 B -> conflict-free LDSM)

__global__ void __launch_bounds__(256) attn_mma(
    const float* __restrict__ Q, const float* __restrict__ K,
    const float* __restrict__ V, float* __restrict__ O)
{
    __shared__ __align__(16) __nv_bfloat16 sbuf[18432];   // 36 KB
    __nv_bfloat16* Qh = sbuf;            // [128][AS]
    __nv_bfloat16* Ql = sbuf + 9216;
    __nv_bfloat16* Kh = sbuf;            // [64][AS]
    __nv_bfloat16* Kl = sbuf + 4608;
    __nv_bfloat16* Vh = sbuf + 9216;
    __nv_bfloat16* Vl = sbuf + 13824;

    const int tid  = threadIdx.x;
    const int lane = tid & 31;
    const int w    = tid >> 5;
    const int q0   = blockIdx.x * 128;
    const int bh   = blockIdx.y;
    const int b    = bh >> 4, h = bh & 15;

    const float* qb = Q + (size_t)b * SEQ * D_MODEL + h * DK;
    const float* kb = K + (size_t)b * SEQ * D_MODEL + h * DK;
    const float* vb = V + (size_t)b * SEQ * D_MODEL + h * DK;

    // ---- stage Q (scaled by 1/8 = rsqrt(dk)), hi/lo split ----
    {
        const int row = tid >> 1;
        const int cg  = (tid & 1) * 32;
        const float* p = qb + (size_t)(q0 + row) * D_MODEL + cg;
        #pragma unroll
        for (int jj = 0; jj < 4; ++jj) {
            float4 v0 = *(const float4*)(p + jj * 8);
            float4 v1 = *(const float4*)(p + jj * 8 + 4);
            float f[8] = {v0.x, v0.y, v0.z, v0.w, v1.x, v1.y, v1.z, v1.w};
            uint32_t hh[4], ll[4];
            #pragma unroll
            for (int j = 0; j < 4; ++j)
                pack_hilo(f[2*j] * 0.125f, f[2*j+1] * 0.125f, hh[j], ll[j]);
            *(uint4*)&Qh[row * AS + cg + jj * 8] = make_uint4(hh[0], hh[1], hh[2], hh[3]);
            *(uint4*)&Ql[row * AS + cg + jj * 8] = make_uint4(ll[0], ll[1], ll[2], ll[3]);
        }
    }
    __syncthreads();

    // ---- extract persistent Q A-fragments (4 k-steps, hi+lo) ----
    const int g    = lane >> 3;
    const int rofs = ((g & 1) << 3) + (lane & 7);
    const int kofs = (g >> 1) << 3;
    uint32_t qfh[4][4], qfl[4][4];
    {
        uint32_t aQh = s2u(Qh) + (((w * 16 + rofs) * AS + kofs) << 1);
        uint32_t aQl = s2u(Ql) + (((w * 16 + rofs) * AS + kofs) << 1);
        #pragma unroll
        for (int ks = 0; ks < 4; ++ks) {
            LDSM_X4(qfh[ks], aQh + ks * 32);
            LDSM_X4(qfl[ks], aQl + ks * 32);
        }
    }
    __syncthreads();   // Q smem free; becomes K/V smem

    const float NEG_INF = __int_as_float(0xff800000);
    float m0 = NEG_INF, m1 = NEG_INF, l0 = 0.f, l1 = 0.f;
    float oc[8][4] = {};

    // B-operand addresses
    const uint32_t aKh = s2u(Kh) + ((rofs * AS + kofs) << 1);
    const uint32_t aKl = s2u(Kl) + ((rofs * AS + kofs) << 1);
    const uint32_t vofs = (((lane & 15) * AS + ((lane >> 4) << 3)) << 1);
    const uint32_t aVh = s2u(Vh) + vofs;
    const uint32_t aVl = s2u(Vl) + vofs;

    // staging indices for K/V
    const int jrow = tid >> 2;
    const int jcg  = (tid & 3) * 16;

    #pragma unroll 1
    for (int it = 0; it < SEQ / 64; ++it) {
        if (it) __syncthreads();

        // ---- stage K, V tile (64 x 64), hi/lo ----
        {
            const float* kp = kb + (size_t)(it * 64 + jrow) * D_MODEL + jcg;
            const float* vp = vb + (size_t)(it * 64 + jrow) * D_MODEL + jcg;
            float fk[16], fv[16];
            #pragma unroll
            for (int j = 0; j < 4; ++j) {
                float4 t = *(const float4*)(kp + j * 4);
                fk[4*j] = t.x; fk[4*j+1] = t.y; fk[4*j+2] = t.z; fk[4*j+3] = t.w;
                t = *(const float4*)(vp + j * 4);
                fv[4*j] = t.x; fv[4*j+1] = t.y; fv[4*j+2] = t.z; fv[4*j+3] = t.w;
            }
            uint32_t hh[8], ll[8];
            #pragma unroll
            for (int j = 0; j < 8; ++j) pack_hilo(fk[2*j], fk[2*j+1], hh[j], ll[j]);
            *(uint4*)&Kh[jrow * AS + jcg]     = make_uint4(hh[0], hh[1], hh[2], hh[3]);
            *(uint4*)&Kh[jrow * AS + jcg + 8] = make_uint4(hh[4], hh[5], hh[6], hh[7]);
            *(uint4*)&Kl[jrow * AS + jcg]     = make_uint4(ll[0], ll[1], ll[2], ll[3]);
            *(uint4*)&Kl[jrow * AS + jcg + 8] = make_uint4(ll[4], ll[5], ll[6], ll[7]);
            #pragma unroll
            for (int j = 0; j < 8; ++j) pack_hilo(fv[2*j], fv[2*j+1], hh[j], ll[j]);
            *(uint4*)&Vh[jrow * AS + jcg]     = make_uint4(hh[0], hh[1], hh[2], hh[3]);
            *(uint4*)&Vh[jrow * AS + jcg + 8] = make_uint4(hh[4], hh[5], hh[6], hh[7]);
            *(uint4*)&Vl[jrow * AS + jcg]     = make_uint4(ll[0], ll[1], ll[2], ll[3]);
            *(uint4*)&Vl[jrow * AS + jcg + 8] = make_uint4(ll[4], ll[5], ll[6], ll[7]);
        }
        __syncthreads();

        // ---- S = Q @ K^T (already scaled) ----
        float sc[8][4] = {};
        #pragma unroll
        for (int ks = 0; ks < 4; ++ks) {
            #pragma unroll
            for (int jg = 0; jg < 4; ++jg) {
                uint32_t kh[4], kl[4];
                LDSM_X4(kh, aKh + jg * (16 * AS * 2) + ks * 32);
                LDSM_X4(kl, aKl + jg * (16 * AS * 2) + ks * 32);
                MMA16816(sc[2*jg],   qfh[ks], kh[0], kh[2]);
                MMA16816(sc[2*jg],   qfh[ks], kl[0], kl[2]);
                MMA16816(sc[2*jg],   qfl[ks], kh[0], kh[2]);
                MMA16816(sc[2*jg+1], qfh[ks], kh[1], kh[3]);
                MMA16816(sc[2*jg+1], qfh[ks], kl[1], kl[3]);
                MMA16816(sc[2*jg+1], qfl[ks], kh[1], kh[3]);
            }
        }

        // ---- online softmax (rows lr and lr+8 of warp tile) ----
        float mx0 = NEG_INF, mx1 = NEG_INF;
        #pragma unroll
        for (int t = 0; t < 8; ++t) {
            mx0 = fmaxf(mx0, fmaxf(sc[t][0], sc[t][1]));
            mx1 = fmaxf(mx1, fmaxf(sc[t][2], sc[t][3]));
        }
        mx0 = fmaxf(mx0, __shfl_xor_sync(0xffffffffu, mx0, 1));
        mx0 = fmaxf(mx0, __shfl_xor_sync(0xffffffffu, mx0, 2));
        mx1 = fmaxf(mx1, __shfl_xor_sync(0xffffffffu, mx1, 1));
        mx1 = fmaxf(mx1, __shfl_xor_sync(0xffffffffu, mx1, 2));

        float mn0 = fmaxf(m0, mx0);
        float mn1 = fmaxf(m1, mx1);
        float e0 = __expf(m0 - mn0);
        float e1 = __expf(m1 - mn1);
        m0 = mn0; m1 = mn1;

        float rs0 = 0.f, rs1 = 0.f;
        #pragma unroll
        for (int t = 0; t < 8; ++t) {
            sc[t][0] = __expf(sc[t][0] - mn0);
            sc[t][1] = __expf(sc[t][1] - mn0);
            sc[t][2] = __expf(sc[t][2] - mn1);
            sc[t][3] = __expf(sc[t][3] - mn1);
            rs0 += sc[t][0] + sc[t][1];
            rs1 += sc[t][2] + sc[t][3];
        }
        rs0 += __shfl_xor_sync(0xffffffffu, rs0, 1);
        rs0 += __shfl_xor_sync(0xffffffffu, rs0, 2);
        rs1 += __shfl_xor_sync(0xffffffffu, rs1, 1);
        rs1 += __shfl_xor_sync(0xffffffffu, rs1, 2);
        l0 = l0 * e0 + rs0;
        l1 = l1 * e1 + rs1;

        #pragma unroll
        for (int t = 0; t < 8; ++t) {
            oc[t][0] *= e0; oc[t][1] *= e0;
            oc[t][2] *= e1; oc[t][3] *= e1;
        }

        // ---- O += P @ V (P hi/lo from C-fragments, V hi/lo via ldsm.trans) ----
        #pragma unroll
        for (int ks = 0; ks < 4; ++ks) {
            uint32_t ph[4], pl[4];
            pack_hilo(sc[2*ks][0],   sc[2*ks][1],   ph[0], pl[0]);
            pack_hilo(sc[2*ks][2],   sc[2*ks][3],   ph[1], pl[1]);
            pack_hilo(sc[2*ks+1][0], sc[2*ks+1][1], ph[2], pl[2]);
            pack_hilo(sc[2*ks+1][2], sc[2*ks+1][3], ph[3], pl[3]);
            #pragma unroll
            for (int dg = 0; dg < 4; ++dg) {
                uint32_t vh[4], vl[4];
                LDSM_X4_T(vh, aVh + ks * (16 * AS * 2) + dg * 32);
                LDSM_X4_T(vl, aVl + ks * (16 * AS * 2) + dg * 32);
                MMA16816(oc[2*dg],   ph, vh[0], vh[1]);
                MMA16816(oc[2*dg],   ph, vl[0], vl[1]);
                MMA16816(oc[2*dg],   pl, vh[0], vh[1]);
                MMA16816(oc[2*dg+1], ph, vh[2], vh[3]);
                MMA16816(oc[2*dg+1], ph, vl[2], vl[3]);
                MMA16816(oc[2*dg+1], pl, vh[2], vh[3]);
            }
        }
    }

    // ---- epilogue: normalize and store ----
    {
        const float inv0 = 1.f / l0;
        const float inv1 = 1.f / l1;
        const int lr = lane >> 2;
        const int lc = (lane & 3) << 1;
        const int row0 = q0 + w * 16 + lr;
        float* ob = O + (size_t)b * SEQ * D_MODEL + h * DK;
        #pragma unroll
        for (int t = 0; t < 8; ++t) {
            const int col = t * 8 + lc;
            float2 r0, r1;
            r0.x = oc[t][0] * inv0; r0.y = oc[t][1] * inv0;
            r1.x = oc[t][2] * inv1; r1.y = oc[t][3] * inv1;
            *(float2*)&ob[(size_t)row0 * D_MODEL + col]       = r0;
            *(float2*)&ob[(size_t)(row0 + 8) * D_MODEL + col] = r1;
        }
    }
}

// ---------------------------------------------------------------------------
extern "C" void kernel_launch(void* const* d_in, const int* in_sizes, int n_in,
                              void* d_out, int out_size)
{
    const float* x  = (const float*)d_in[0];
    const float* Wq = (const float*)d_in[1];
    const float* bq = (const float*)d_in[2];
    const float* Wk = (const float*)d_in[3];
    const float* bk = (const float*)d_in[4];
    const float* Wv = (const float*)d_in[5];
    const float* bv = (const float*)d_in[6];
    const float* Wo = (const float*)d_in[7];
    const float* bo = (const float*)d_in[8];
    float* out = (float*)d_out;

    float *gq, *gk, *gv, *gctx;
    cudaGetSymbolAddress((void**)&gq,   g_Q);
    cudaGetSymbolAddress((void**)&gk,   g_K);
    cudaGetSymbolAddress((void**)&gv,   g_V);
    cudaGetSymbolAddress((void**)&gctx, g_CTX);

    dim3 gg(D_MODEL / 128, MTOT / 128);   // (8, 32)
    gemm_mma<<<gg, 256>>>(x, Wq, bq, gq);
    gemm_mma<<<gg, 256>>>(x, Wk, bk, gk);
    gemm_mma<<<gg, 256>>>(x, Wv, bv, gv);
    attn_mma<<<dim3(SEQ / 128, BATCH * NHEAD), 256>>>(gq, gk, gv, gctx);
    gemm_mma<<<gg, 256>>>(gctx, Wo, bo, out);
}

// round 5
// speedup vs baseline: 2.6795x; 1.1174x over previous
#include <cuda_runtime.h>
#include <cuda_bf16.h>
#include <math.h>
#include <stdint.h>

#define D_MODEL 1024
#define NHEAD   16
#define DK      64
#define BATCH   2
#define SEQ     2048
#define MTOT    (BATCH*SEQ)   // 4096

typedef __nv_bfloat16 bf16;

// ---------------------------------------------------------------------------
// Scratch (allocation-free: __device__ globals). All hi/lo bf16 pairs.
// ---------------------------------------------------------------------------
__device__ bf16 g_xh[MTOT * D_MODEL],  g_xl[MTOT * D_MODEL];
__device__ bf16 g_Wqh[D_MODEL * D_MODEL], g_Wql[D_MODEL * D_MODEL];
__device__ bf16 g_Wkh[D_MODEL * D_MODEL], g_Wkl[D_MODEL * D_MODEL];
__device__ bf16 g_Wvh[D_MODEL * D_MODEL], g_Wvl[D_MODEL * D_MODEL];
__device__ bf16 g_Woh[D_MODEL * D_MODEL], g_Wol[D_MODEL * D_MODEL];
__device__ bf16 g_Qh[MTOT * D_MODEL],  g_Ql[MTOT * D_MODEL];
__device__ bf16 g_Kh[MTOT * D_MODEL],  g_Kl[MTOT * D_MODEL];
__device__ bf16 g_Vh[MTOT * D_MODEL],  g_Vl[MTOT * D_MODEL];
__device__ bf16 g_Ch[MTOT * D_MODEL],  g_Cl[MTOT * D_MODEL];

// ============================================================================
// helpers
// ============================================================================
__device__ __forceinline__ uint32_t s2u(const void* p) {
    uint32_t a;
    asm("{ .reg .u64 t; cvta.to.shared.u64 t, %1; cvt.u32.u64 %0, t; }"
        : "=r"(a) : "l"(p));
    return a;
}

#define LDSM_X4(R, addr)                                                    \
    asm volatile("ldmatrix.sync.aligned.m8n8.x4.shared.b16 "                \
                 "{%0,%1,%2,%3}, [%4];"                                     \
                 : "=r"((R)[0]), "=r"((R)[1]), "=r"((R)[2]), "=r"((R)[3])   \
                 : "r"(addr))

#define LDSM_X4_T(R, addr)                                                  \
    asm volatile("ldmatrix.sync.aligned.m8n8.x4.trans.shared.b16 "          \
                 "{%0,%1,%2,%3}, [%4];"                                     \
                 : "=r"((R)[0]), "=r"((R)[1]), "=r"((R)[2]), "=r"((R)[3])   \
                 : "r"(addr))

#define MMA16816(C, A, B0, B1)                                              \
    asm volatile("mma.sync.aligned.m16n8k16.row.col.f32.bf16.bf16.f32 "     \
                 "{%0,%1,%2,%3}, {%4,%5,%6,%7}, {%8,%9}, {%0,%1,%2,%3};"    \
                 : "+f"((C)[0]), "+f"((C)[1]), "+f"((C)[2]), "+f"((C)[3])   \
                 : "r"((A)[0]), "r"((A)[1]), "r"((A)[2]), "r"((A)[3]),      \
                   "r"(B0), "r"(B1))

__device__ __forceinline__ void pack_hilo(float a, float b,
                                          uint32_t& h, uint32_t& l) {
    __nv_bfloat162 hv;
    hv.x = __float2bfloat16(a);
    hv.y = __float2bfloat16(b);
    float ra = a - __bfloat162float(hv.x);
    float rb = b - __bfloat162float(hv.y);
    __nv_bfloat162 lv;
    lv.x = __float2bfloat16(ra);
    lv.y = __float2bfloat16(rb);
    h = *(uint32_t*)&hv;
    l = *(uint32_t*)&lv;
}

// ============================================================================
// fp32 -> hi/lo bf16 elementwise split (memory-bound)
// ============================================================================
__global__ void __launch_bounds__(256) conv_hilo(
    const float* __restrict__ src, bf16* __restrict__ h,
    bf16* __restrict__ l, int n)
{
    int i = (blockIdx.x * 256 + threadIdx.x) * 4;
    if (i < n) {
        float4 v = *(const float4*)(src + i);
        uint32_t h0, h1, l0, l1;
        pack_hilo(v.x, v.y, h0, l0);
        pack_hilo(v.z, v.w, h1, l1);
        *(uint2*)&h[i] = make_uint2(h0, h1);
        *(uint2*)&l[i] = make_uint2(l0, l1);
    }
}

// ============================================================================
// HMMA GEMM, all-bf16 hi/lo inputs:
//   C[M][N] = (Ah+Al)[M][K] @ (Wh+Wl)[N][K]^T + bias[N]    (M=4096, N=K=1024)
// MODE 0: write fp32 C. MODE 1: write hi/lo bf16 (Ch, Cl), scaled.
// CTA 128x128, K-stage 32, 256 threads = 8 warps (4m x 2n).
// ============================================================================
#define RS 40                      // bf16 elements per smem row (80 B)

template <int MODE>
__global__ void __launch_bounds__(256) gemm_hilo(
    const bf16* __restrict__ Ah, const bf16* __restrict__ Al,
    const bf16* __restrict__ Wh, const bf16* __restrict__ Wl,
    const float* __restrict__ bias, float scale,
    float* __restrict__ C, bf16* __restrict__ Ch, bf16* __restrict__ Cl)
{
    __shared__ __align__(16) bf16 sAh[128 * RS];
    __shared__ __align__(16) bf16 sAl[128 * RS];
    __shared__ __align__(16) bf16 sWh[128 * RS];
    __shared__ __align__(16) bf16 sWl[128 * RS];

    const int tid  = threadIdx.x;
    const int lane = tid & 31;
    const int wid  = tid >> 5;
    const int wm   = wid & 3;
    const int wn   = wid >> 2;
    const int m0   = blockIdx.y * 128;
    const int n0   = blockIdx.x * 128;

    float acc[2][8][4] = {};

    const int g    = lane >> 3;
    const int rofs = ((g & 1) << 3) + (lane & 7);
    const int kofs = (g >> 1) << 3;

    const uint32_t aH = s2u(sAh) + (((wm * 32 + rofs) * RS + kofs) << 1);
    const uint32_t aL = s2u(sAl) + (((wm * 32 + rofs) * RS + kofs) << 1);
    const uint32_t bH = s2u(sWh) + (((wn * 64 + rofs) * RS + kofs) << 1);
    const uint32_t bL = s2u(sWl) + (((wn * 64 + rofs) * RS + kofs) << 1);

    // staging: thread -> (row, 16-elem k-half); 16 bf16 = 2 uint4 per array
    const int srow = tid >> 1;
    const int skh  = (tid & 1) << 4;
    const size_t gofsA = (size_t)(m0 + srow) * D_MODEL + skh;
    const size_t gofsW = (size_t)(n0 + srow) * D_MODEL + skh;

    uint4 pa[2][2], pw[2][2];
    {
        pa[0][0] = *(const uint4*)(Ah + gofsA);
        pa[0][1] = *(const uint4*)(Ah + gofsA + 8);
        pa[1][0] = *(const uint4*)(Al + gofsA);
        pa[1][1] = *(const uint4*)(Al + gofsA + 8);
        pw[0][0] = *(const uint4*)(Wh + gofsW);
        pw[0][1] = *(const uint4*)(Wh + gofsW + 8);
        pw[1][0] = *(const uint4*)(Wl + gofsW);
        pw[1][1] = *(const uint4*)(Wl + gofsW + 8);
    }

    #pragma unroll 1
    for (int s = 0; s < 32; ++s) {
        if (s) __syncthreads();

        *(uint4*)&sAh[srow * RS + skh]     = pa[0][0];
        *(uint4*)&sAh[srow * RS + skh + 8] = pa[0][1];
        *(uint4*)&sAl[srow * RS + skh]     = pa[1][0];
        *(uint4*)&sAl[srow * RS + skh + 8] = pa[1][1];
        *(uint4*)&sWh[srow * RS + skh]     = pw[0][0];
        *(uint4*)&sWh[srow * RS + skh + 8] = pw[0][1];
        *(uint4*)&sWl[srow * RS + skh]     = pw[1][0];
        *(uint4*)&sWl[srow * RS + skh + 8] = pw[1][1];

        if (s + 1 < 32) {
            const size_t oa = gofsA + (s + 1) * 32;
            const size_t ow = gofsW + (s + 1) * 32;
            pa[0][0] = *(const uint4*)(Ah + oa);
            pa[0][1] = *(const uint4*)(Ah + oa + 8);
            pa[1][0] = *(const uint4*)(Al + oa);
            pa[1][1] = *(const uint4*)(Al + oa + 8);
            pw[0][0] = *(const uint4*)(Wh + ow);
            pw[0][1] = *(const uint4*)(Wh + ow + 8);
            pw[1][0] = *(const uint4*)(Wl + ow);
            pw[1][1] = *(const uint4*)(Wl + ow + 8);
        }
        __syncthreads();

        #pragma unroll
        for (int kk = 0; kk < 2; ++kk) {
            const uint32_t ko = kk << 5;
            uint32_t ah[2][4], al[2][4];
            LDSM_X4(ah[0], aH + ko);
            LDSM_X4(ah[1], aH + 16 * RS * 2 + ko);
            LDSM_X4(al[0], aL + ko);
            LDSM_X4(al[1], aL + 16 * RS * 2 + ko);
            #pragma unroll
            for (int ng = 0; ng < 4; ++ng) {
                uint32_t bh[4], bl[4];
                LDSM_X4(bh, bH + ng * 16 * RS * 2 + ko);
                LDSM_X4(bl, bL + ng * 16 * RS * 2 + ko);
                #pragma unroll
                for (int mt = 0; mt < 2; ++mt) {
                    MMA16816(acc[mt][2*ng],   ah[mt], bh[0], bh[2]);
                    MMA16816(acc[mt][2*ng],   ah[mt], bl[0], bl[2]);
                    MMA16816(acc[mt][2*ng],   al[mt], bh[0], bh[2]);
                    MMA16816(acc[mt][2*ng+1], ah[mt], bh[1], bh[3]);
                    MMA16816(acc[mt][2*ng+1], ah[mt], bl[1], bl[3]);
                    MMA16816(acc[mt][2*ng+1], al[mt], bh[1], bh[3]);
                }
            }
        }
    }

    const int lr = lane >> 2;
    const int lc = (lane & 3) << 1;
    #pragma unroll
    for (int mt = 0; mt < 2; ++mt) {
        const int row = m0 + wm * 32 + mt * 16 + lr;
        #pragma unroll
        for (int nt = 0; nt < 8; ++nt) {
            const int col = n0 + wn * 64 + nt * 8 + lc;
            float2 bb = *(const float2*)&bias[col];
            float r0x = acc[mt][nt][0] + bb.x;
            float r0y = acc[mt][nt][1] + bb.y;
            float r1x = acc[mt][nt][2] + bb.x;
            float r1y = acc[mt][nt][3] + bb.y;
            if (MODE == 0) {
                *(float2*)&C[(size_t)row * D_MODEL + col]       = make_float2(r0x, r0y);
                *(float2*)&C[(size_t)(row + 8) * D_MODEL + col] = make_float2(r1x, r1y);
            } else {
                uint32_t hh, ll;
                pack_hilo(r0x * scale, r0y * scale, hh, ll);
                *(uint32_t*)&Ch[(size_t)row * D_MODEL + col] = hh;
                *(uint32_t*)&Cl[(size_t)row * D_MODEL + col] = ll;
                pack_hilo(r1x * scale, r1y * scale, hh, ll);
                *(uint32_t*)&Ch[(size_t)(row + 8) * D_MODEL + col] = hh;
                *(uint32_t*)&Cl[(size_t)(row + 8) * D_MODEL + col] = ll;
            }
        }
    }
}

// ============================================================================
// HMMA flash attention, all inputs pre-split hi/lo bf16.
// CTA: 128 q rows x one (b,h). 8 warps x 16 q rows. KV tile 64.
// Output ctx written as hi/lo bf16 for the final GEMM.
// ============================================================================
#define AS 72    // smem row stride in bf16 (144 B)

__global__ void __launch_bounds__(256, 2) attn_mma(
    const bf16* __restrict__ Qh, const bf16* __restrict__ Ql,
    const bf16* __restrict__ Kh, const bf16* __restrict__ Kl,
    const bf16* __restrict__ Vh, const bf16* __restrict__ Vl,
    bf16* __restrict__ Oh, bf16* __restrict__ Ol)
{
    __shared__ __align__(16) bf16 sbuf[18432];   // 36 KB
    bf16* sQh = sbuf;            // [128][AS]
    bf16* sQl = sbuf + 9216;
    bf16* sKh = sbuf;            // [64][AS]
    bf16* sKl = sbuf + 4608;
    bf16* sVh = sbuf + 9216;
    bf16* sVl = sbuf + 13824;

    const int tid  = threadIdx.x;
    const int lane = tid & 31;
    const int w    = tid >> 5;
    const int q0   = blockIdx.x * 128;
    const int bh   = blockIdx.y;
    const int b    = bh >> 4, h = bh & 15;
    const size_t base = (size_t)b * SEQ * D_MODEL + h * DK;

    // ---- stage Q (pre-scaled, pre-split) ----
    {
        const int row = tid >> 1;
        const int cg  = (tid & 1) * 32;
        const size_t go = base + (size_t)(q0 + row) * D_MODEL + cg;
        #pragma unroll
        for (int j = 0; j < 4; ++j) {
            *(uint4*)&sQh[row * AS + cg + j * 8] = *(const uint4*)(Qh + go + j * 8);
            *(uint4*)&sQl[row * AS + cg + j * 8] = *(const uint4*)(Ql + go + j * 8);
        }
    }
    __syncthreads();

    // ---- persistent Q A-fragments ----
    const int g    = lane >> 3;
    const int rofs = ((g & 1) << 3) + (lane & 7);
    const int kofs = (g >> 1) << 3;
    uint32_t qfh[4][4], qfl[4][4];
    {
        uint32_t aQh = s2u(sQh) + (((w * 16 + rofs) * AS + kofs) << 1);
        uint32_t aQl = s2u(sQl) + (((w * 16 + rofs) * AS + kofs) << 1);
        #pragma unroll
        for (int ks = 0; ks < 4; ++ks) {
            LDSM_X4(qfh[ks], aQh + ks * 32);
            LDSM_X4(qfl[ks], aQl + ks * 32);
        }
    }
    __syncthreads();   // Q smem free; becomes K/V smem

    const float NEG_INF = __int_as_float(0xff800000);
    float m0 = NEG_INF, m1 = NEG_INF, l0 = 0.f, l1 = 0.f;
    float oc[8][4] = {};

    const uint32_t aKh = s2u(sKh) + ((rofs * AS + kofs) << 1);
    const uint32_t aKl = s2u(sKl) + ((rofs * AS + kofs) << 1);
    const uint32_t vofs = (((lane & 15) * AS + ((lane >> 4) << 3)) << 1);
    const uint32_t aVh = s2u(sVh) + vofs;
    const uint32_t aVl = s2u(sVl) + vofs;

    const int jrow = tid >> 2;
    const int jcg  = (tid & 3) * 16;

    #pragma unroll 1
    for (int it = 0; it < SEQ / 64; ++it) {
        if (it) __syncthreads();

        // ---- stage K, V tile (pure copy) ----
        {
            const size_t go = base + (size_t)(it * 64 + jrow) * D_MODEL + jcg;
            *(uint4*)&sKh[jrow * AS + jcg]     = *(const uint4*)(Kh + go);
            *(uint4*)&sKh[jrow * AS + jcg + 8] = *(const uint4*)(Kh + go + 8);
            *(uint4*)&sKl[jrow * AS + jcg]     = *(const uint4*)(Kl + go);
            *(uint4*)&sKl[jrow * AS + jcg + 8] = *(const uint4*)(Kl + go + 8);
            *(uint4*)&sVh[jrow * AS + jcg]     = *(const uint4*)(Vh + go);
            *(uint4*)&sVh[jrow * AS + jcg + 8] = *(const uint4*)(Vh + go + 8);
            *(uint4*)&sVl[jrow * AS + jcg]     = *(const uint4*)(Vl + go);
            *(uint4*)&sVl[jrow * AS + jcg + 8] = *(const uint4*)(Vl + go + 8);
        }
        __syncthreads();

        // ---- S = Q @ K^T ----
        float sc[8][4] = {};
        #pragma unroll
        for (int ks = 0; ks < 4; ++ks) {
            #pragma unroll
            for (int jg = 0; jg < 4; ++jg) {
                uint32_t kh[4], kl[4];
                LDSM_X4(kh, aKh + jg * (16 * AS * 2) + ks * 32);
                LDSM_X4(kl, aKl + jg * (16 * AS * 2) + ks * 32);
                MMA16816(sc[2*jg],   qfh[ks], kh[0], kh[2]);
                MMA16816(sc[2*jg],   qfh[ks], kl[0], kl[2]);
                MMA16816(sc[2*jg],   qfl[ks], kh[0], kh[2]);
                MMA16816(sc[2*jg+1], qfh[ks], kh[1], kh[3]);
                MMA16816(sc[2*jg+1], qfh[ks], kl[1], kl[3]);
                MMA16816(sc[2*jg+1], qfl[ks], kh[1], kh[3]);
            }
        }

        // ---- online softmax ----
        float mx0 = NEG_INF, mx1 = NEG_INF;
        #pragma unroll
        for (int t = 0; t < 8; ++t) {
            mx0 = fmaxf(mx0, fmaxf(sc[t][0], sc[t][1]));
            mx1 = fmaxf(mx1, fmaxf(sc[t][2], sc[t][3]));
        }
        mx0 = fmaxf(mx0, __shfl_xor_sync(0xffffffffu, mx0, 1));
        mx0 = fmaxf(mx0, __shfl_xor_sync(0xffffffffu, mx0, 2));
        mx1 = fmaxf(mx1, __shfl_xor_sync(0xffffffffu, mx1, 1));
        mx1 = fmaxf(mx1, __shfl_xor_sync(0xffffffffu, mx1, 2));

        float mn0 = fmaxf(m0, mx0);
        float mn1 = fmaxf(m1, mx1);
        float e0 = __expf(m0 - mn0);
        float e1 = __expf(m1 - mn1);
        m0 = mn0; m1 = mn1;

        float rs0 = 0.f, rs1 = 0.f;
        #pragma unroll
        for (int t = 0; t < 8; ++t) {
            sc[t][0] = __expf(sc[t][0] - mn0);
            sc[t][1] = __expf(sc[t][1] - mn0);
            sc[t][2] = __expf(sc[t][2] - mn1);
            sc[t][3] = __expf(sc[t][3] - mn1);
            rs0 += sc[t][0] + sc[t][1];
            rs1 += sc[t][2] + sc[t][3];
        }
        rs0 += __shfl_xor_sync(0xffffffffu, rs0, 1);
        rs0 += __shfl_xor_sync(0xffffffffu, rs0, 2);
        rs1 += __shfl_xor_sync(0xffffffffu, rs1, 1);
        rs1 += __shfl_xor_sync(0xffffffffu, rs1, 2);
        l0 = l0 * e0 + rs0;
        l1 = l1 * e1 + rs1;

        #pragma unroll
        for (int t = 0; t < 8; ++t) {
            oc[t][0] *= e0; oc[t][1] *= e0;
            oc[t][2] *= e1; oc[t][3] *= e1;
        }

        // ---- O += P @ V ----
        #pragma unroll
        for (int ks = 0; ks < 4; ++ks) {
            uint32_t ph[4], pl[4];
            pack_hilo(sc[2*ks][0],   sc[2*ks][1],   ph[0], pl[0]);
            pack_hilo(sc[2*ks][2],   sc[2*ks][3],   ph[1], pl[1]);
            pack_hilo(sc[2*ks+1][0], sc[2*ks+1][1], ph[2], pl[2]);
            pack_hilo(sc[2*ks+1][2], sc[2*ks+1][3], ph[3], pl[3]);
            #pragma unroll
            for (int dg = 0; dg < 4; ++dg) {
                uint32_t vh[4], vl[4];
                LDSM_X4_T(vh, aVh + ks * (16 * AS * 2) + dg * 32);
                LDSM_X4_T(vl, aVl + ks * (16 * AS * 2) + dg * 32);
                MMA16816(oc[2*dg],   ph, vh[0], vh[1]);
                MMA16816(oc[2*dg],   ph, vl[0], vl[1]);
                MMA16816(oc[2*dg],   pl, vh[0], vh[1]);
                MMA16816(oc[2*dg+1], ph, vh[2], vh[3]);
                MMA16816(oc[2*dg+1], ph, vl[2], vl[3]);
                MMA16816(oc[2*dg+1], pl, vh[2], vh[3]);
            }
        }
    }

    // ---- epilogue: normalize, split, store hi/lo ctx ----
    {
        const float inv0 = 1.f / l0;
        const float inv1 = 1.f / l1;
        const int lr = lane >> 2;
        const int lc = (lane & 3) << 1;
        const int row0 = q0 + w * 16 + lr;
        #pragma unroll
        for (int t = 0; t < 8; ++t) {
            const int col = t * 8 + lc;
            uint32_t hh, ll;
            pack_hilo(oc[t][0] * inv0, oc[t][1] * inv0, hh, ll);
            *(uint32_t*)&Oh[base + (size_t)row0 * D_MODEL + col] = hh;
            *(uint32_t*)&Ol[base + (size_t)row0 * D_MODEL + col] = ll;
            pack_hilo(oc[t][2] * inv1, oc[t][3] * inv1, hh, ll);
            *(uint32_t*)&Oh[base + (size_t)(row0 + 8) * D_MODEL + col] = hh;
            *(uint32_t*)&Ol[base + (size_t)(row0 + 8) * D_MODEL + col] = ll;
        }
    }
}

// ---------------------------------------------------------------------------
extern "C" void kernel_launch(void* const* d_in, const int* in_sizes, int n_in,
                              void* d_out, int out_size)
{
    const float* x  = (const float*)d_in[0];
    const float* Wq = (const float*)d_in[1];
    const float* bq = (const float*)d_in[2];
    const float* Wk = (const float*)d_in[3];
    const float* bk = (const float*)d_in[4];
    const float* Wv = (const float*)d_in[5];
    const float* bv = (const float*)d_in[6];
    const float* Wo = (const float*)d_in[7];
    const float* bo = (const float*)d_in[8];
    float* out = (float*)d_out;

    bf16 *xh, *xl, *wqh, *wql, *wkh, *wkl, *wvh, *wvl, *woh, *wol;
    bf16 *qh, *ql, *kh, *kl, *vh, *vl, *ch, *cl;
    cudaGetSymbolAddress((void**)&xh,  g_xh);  cudaGetSymbolAddress((void**)&xl,  g_xl);
    cudaGetSymbolAddress((void**)&wqh, g_Wqh); cudaGetSymbolAddress((void**)&wql, g_Wql);
    cudaGetSymbolAddress((void**)&wkh, g_Wkh); cudaGetSymbolAddress((void**)&wkl, g_Wkl);
    cudaGetSymbolAddress((void**)&wvh, g_Wvh); cudaGetSymbolAddress((void**)&wvl, g_Wvl);
    cudaGetSymbolAddress((void**)&woh, g_Woh); cudaGetSymbolAddress((void**)&wol, g_Wol);
    cudaGetSymbolAddress((void**)&qh,  g_Qh);  cudaGetSymbolAddress((void**)&ql,  g_Ql);
    cudaGetSymbolAddress((void**)&kh,  g_Kh);  cudaGetSymbolAddress((void**)&kl,  g_Kl);
    cudaGetSymbolAddress((void**)&vh,  g_Vh);  cudaGetSymbolAddress((void**)&vl,  g_Vl);
    cudaGetSymbolAddress((void**)&ch,  g_Ch);  cudaGetSymbolAddress((void**)&cl,  g_Cl);

    const int NX = MTOT * D_MODEL;       // 4M
    const int NW = D_MODEL * D_MODEL;    // 1M
    conv_hilo<<<NX / 1024, 256>>>(x,  xh,  xl,  NX);
    conv_hilo<<<NW / 1024, 256>>>(Wq, wqh, wql, NW);
    conv_hilo<<<NW / 1024, 256>>>(Wk, wkh, wkl, NW);
    conv_hilo<<<NW / 1024, 256>>>(Wv, wvh, wvl, NW);
    conv_hilo<<<NW / 1024, 256>>>(Wo, woh, wol, NW);

    dim3 gg(D_MODEL / 128, MTOT / 128);   // (8, 32)
    gemm_hilo<1><<<gg, 256>>>(xh, xl, wqh, wql, bq, 0.125f, nullptr, qh, ql);
    gemm_hilo<1><<<gg, 256>>>(xh, xl, wkh, wkl, bk, 1.0f,   nullptr, kh, kl);
    gemm_hilo<1><<<gg, 256>>>(xh, xl, wvh, wvl, bv, 1.0f,   nullptr, vh, vl);
    attn_mma<<<dim3(SEQ / 128, BATCH * NHEAD), 256>>>(qh, ql, kh, kl, vh, vl, ch, cl);
    gemm_hilo<0><<<gg, 256>>>(ch, cl, woh, wol, bo, 1.0f, out, nullptr, nullptr);
}